// round 7
// baseline (speedup 1.0000x reference)
#include <cuda_runtime.h>

#define NATOM 24
#define NSP 4
#define OUTW 384          // 64 radial + 320 angular
#define RADW 64
#define WARPS 8           // centers per block (1 per warp)
#define THREADS 256

// 0.5*cos / 0.5*sin of SHF_Z[t] = (t+0.5)*pi/8 folded later; store raw cos/sin
__constant__ float COSZ[8] = {
     0.980785280403230449f,  0.831469612302545237f,  0.555570233019602225f,  0.195090322016128268f,
    -0.195090322016128268f, -0.555570233019602225f, -0.831469612302545237f, -0.980785280403230449f };
__constant__ float SINZ[8] = {
     0.195090322016128268f,  0.555570233019602225f,  0.831469612302545237f,  0.980785280403230449f,
     0.980785280403230449f,  0.831469612302545237f,  0.555570233019602225f,  0.195090322016128268f };

__global__ __launch_bounds__(THREADS)
void aev_kernel(const int* __restrict__ g_species,
                const float* __restrict__ g_coords,
                float* __restrict__ g_out, int M)
{
    const int bid   = blockIdx.x;
    const int m     = bid / 3;
    const int ibase = (bid - m * 3) * WARPS;

    __shared__ float  sc[NATOM][3];
    __shared__ int    ssp[NATOM];
    __shared__ float  sd  [WARPS][NATOM];   // dist to all 24 (radial)
    __shared__ float  sfcr[WARPS][NATOM];   // radial cutoff fn
    __shared__ float4 cu  [WARPS][NATOM];   // compacted: ux,uy,uz,d
    __shared__ float2 cf  [WARPS][NATOM];   // compacted: fca, species(bits)
    __shared__ float  acc [WARPS][OUTW];    // 12 KB

    const int tid  = threadIdx.x;
    const int lane = tid & 31;
    const int w    = tid >> 5;
    const int ic   = ibase + w;             // this warp's center atom

    // ---- init ---------------------------------------------------------
    if (tid < NATOM) {
        ssp[tid]   = g_species[m * NATOM + tid];
        sc[tid][0] = g_coords[(m * NATOM + tid) * 3 + 0];
        sc[tid][1] = g_coords[(m * NATOM + tid) * 3 + 1];
        sc[tid][2] = g_coords[(m * NATOM + tid) * 3 + 2];
    }
    #pragma unroll
    for (int idx = lane; idx < OUTW; idx += 32) acc[w][idx] = 0.0f;
    __syncthreads();

    // ---- step 1: per-neighbor screen (lane = neighbor j) ---------------
    bool  live = false;
    float fca = 0.f, d = 1.f, dx = 0.f, dy = 0.f, dz = 0.f;
    int   spj = 0;
    if (lane < NATOM) {
        int j = lane;
        dx = sc[j][0] - sc[ic][0];
        dy = sc[j][1] - sc[ic][1];
        dz = sc[j][2] - sc[ic][2];
        float d2 = dx * dx + dy * dy + dz * dz;
        bool ok = (j != ic);
        d = ok ? sqrtf(d2) : 1.0f;
        fca        = (ok && d <= 3.5f) ? (0.5f * __cosf(0.897597901025655210f * d) + 0.5f) : 0.0f;
        float fcr  = (ok && d <= 5.2f) ? (0.5f * __cosf(0.604152493782718100f * d) + 0.5f) : 0.0f;
        sd[w][j]   = d;
        sfcr[w][j] = fcr;
        spj = ssp[j];
        live = (fca > 0.0f);
    }
    unsigned mask = __ballot_sync(0xffffffffu, live);
    if (live) {
        int pos = __popc(mask & ((1u << lane) - 1u));
        float rd = 1.0f / d;
        cu[w][pos] = make_float4(dx * rd, dy * rd, dz * rd, d);
        cf[w][pos] = make_float2(fca, __int_as_float(spj));
    }
    const int nn = __popc(mask);
    __syncwarp();

    // ---- step 2: radial (lanes: r = lane&15, two j's per iter) ---------
    {
        int   r    = lane & 15;
        int   half = lane >> 4;
        float shfr = 0.9f + 0.26875f * (float)r;
        #pragma unroll
        for (int it = 0; it < 12; it++) {
            int   j   = it * 2 + half;
            float dd  = sd[w][j];
            float fcr = sfcr[w][j];
            if (fcr > 0.0f) {
                float u = dd - shfr;
                float v = 0.25f * fcr * __expf(-16.0f * u * u);
                atomicAdd(&acc[w][ssp[j] * 16 + r], v);
            }
        }
    }

    // ---- step 3: angular over compacted pairs --------------------------
    {
        const int   a_l  = lane >> 3;           // SHF_A index
        const int   z_l  = lane & 7;            // SHF_Z index
        const float czc  = 0.5f * COSZ[z_l];
        const float szc  = 0.5f * SINZ[z_l];
        const float shfa = 0.9f + 0.65f * (float)a_l;

        for (int a = 0; a < nn - 1; a++) {
            float4 ua  = cu[w][a];
            float2 fa  = cf[w][a];
            int    spa = __float_as_int(fa.y);
            for (int b = a + 1; b < nn; b++) {
                float4 ub  = cu[w][b];
                float2 fb  = cf[w][b];
                int    spb = __float_as_int(fb.y);
                float c    = 0.95f * (ua.x * ub.x + ua.y * ub.y + ua.z * ub.z);
                float s    = sqrtf(fmaxf(0.0f, 1.0f - c * c));
                float davg = 0.5f * (ua.w + ub.w);
                float w2   = 2.0f * fa.x * fb.x;
                int lo = min(spa, spb), hi = max(spa, spb);
                int pidx = lo * NSP - ((lo * (lo - 1)) >> 1) + (hi - lo);

                float cz = 0.5f + c * czc + s * szc;
                float x = cz * cz;   // ^2
                x = x * x;           // ^4
                x = x * x;           // ^8
                x = x * x;           // ^16
                x = x * x;           // ^32
                float u   = davg - shfa;
                float val = w2 * x * __expf(-8.0f * u * u);
                atomicAdd(&acc[w][RADW + pidx * 32 + a_l * 8 + z_l], val);
            }
        }
    }
    __syncthreads();

    // ---- writeout ------------------------------------------------------
    const float* src = &acc[0][0];
    float* dstg = g_out + ((size_t)m * NATOM + ibase) * OUTW;
    for (int idx = tid; idx < WARPS * OUTW; idx += THREADS)
        dstg[idx] = src[idx];
}

extern "C" void kernel_launch(void* const* d_in, const int* in_sizes, int n_in,
                              void* d_out, int out_size)
{
    const int*   species = (const int*)d_in[0];
    const float* coords  = (const float*)d_in[1];
    int M = in_sizes[0] / NATOM;
    aev_kernel<<<M * 3, THREADS>>>(species, coords, (float*)d_out, M);
}